// round 13
// baseline (speedup 1.0000x reference)
#include <cuda_runtime.h>
#include <cuda_bf16.h>
#include <math.h>

#define BATCH 256
#define NV 27
#define DMODEL 256
#define FFDIM 1024
#define NLAYERS 3
#define THREADS 512

// pitches
#define TLDW 260           // fp32 activation pitch (words), %32==4 -> conflict-free
#define KLDE 258           // bf16 k/v pitch (elements)
#define HLDW 132           // fp32 h-chunk pitch (words), %32==4
// byte offsets in dynamic SMEM (M32: 32-row activation buffers, 27 real rows)
#define B_T 0                          // t: 32 x 260 f32 = 33280
#define B_X 33280                      // x: 32 x 260 f32 = 33280
#define B_KV 66560                     // k: 27 x 258 bf16 = 13932 -> 13952
#define B_V (B_KV + 13952)             // v: 13952
#define B_RING (B_KV + 27904)          // ring: 2 x 8 x 264 f32 = 16896
#define B_MSK (B_RING + 16896)         // msk: 27 x 28 = 756
#define B_NBR (B_MSK + 756)            // nbrt: 756
#define SMEM_BYTES (B_NBR + 756 + 16)  // ~112.9 KB -> 2 CTAs/SM

__device__ int   g_mode;
__device__ float g_zero[DMODEL];   // zero-initialized

// ---------------- mask dtype sniffer ----------------------------------------
__global__ void detect_kernel(const unsigned char* __restrict__ km) {
    __shared__ int cnt1, cnt3f;
    if (threadIdx.x == 0) { cnt1 = 0; cnt3f = 0; }
    __syncthreads();
    int l1 = 0, l3 = 0;
    for (int i = threadIdx.x; i < (BATCH * NV) / 4; i += blockDim.x) {
        if (km[4 * i + 1] != 0) l1++;
        if (km[4 * i + 3] == 0x3F) l3++;
    }
    atomicAdd(&cnt1, l1);
    atomicAdd(&cnt3f, l3);
    __syncthreads();
    if (threadIdx.x == 0) {
        if (cnt1 > 0)       g_mode = 0;
        else if (cnt3f > 0) g_mode = 2;
        else                g_mode = 1;
    }
}

// ---------------- cp.async helpers -------------------------------------------
__device__ __forceinline__ void cp_async16(void* smem, const void* gmem) {
    unsigned s = (unsigned)__cvta_generic_to_shared(smem);
    asm volatile("cp.async.cg.shared.global [%0], [%1], 16;" :: "r"(s), "l"(gmem));
}
__device__ __forceinline__ void cp_commit() {
    asm volatile("cp.async.commit_group;");
}
template <int N>
__device__ __forceinline__ void cp_wait() {
    asm volatile("cp.async.wait_group %0;" :: "n"(N));
}

// ---------------- CTA GEMM: C[32 x NCOLS] = A[32 x K] @ B[K x NCOLS] ----------
// 16 warps, warp w owns N cols [w*NCOLS/16, +NCOLS/16). 2-stage BK=8 ring,
// load of tile kt+1 overlaps compute of tile kt. Output rows >= 27 discarded.
// EPI: 0 = bias->f32, 1 = f32 accumulate, 2 = gelu->f32, 3 = bf16 store
template <int EPI, int NKT, int NCOLS, int ALDW, int CLDW>
__device__ __noinline__ void cta_gemm(const float* __restrict__ Asm,
                                      const float* __restrict__ Bg, int ldB,
                                      const float* __restrict__ bias,
                                      float* __restrict__ Cs,
                                      float* __restrict__ ring) {
    constexpr int WLDW = (NCOLS == 256) ? 264 : 136;
    constexpr int NSL  = NCOLS / 16;     // 16 or 8
    constexpr int NI   = NSL / 8;        // 2 or 1

    int tid  = threadIdx.x;
    int lane = tid & 31;
    int warp = tid >> 5;
    int grp  = lane >> 2;
    int quad = lane & 3;

    float c[2][NI][4];
    #pragma unroll
    for (int mi = 0; mi < 2; mi++)
        #pragma unroll
        for (int ni = 0; ni < NI; ni++)
            #pragma unroll
            for (int r = 0; r < 4; r++) c[mi][ni][r] = 0.0f;

    auto issue = [&](int kt, int st) {
        if (NCOLS == 256) {
            int lr = tid >> 6, lc = (tid & 63) * 4;
            cp_async16(ring + st * (8 * WLDW) + lr * WLDW + lc,
                       Bg + (size_t)(kt * 8 + lr) * ldB + lc);
        } else {
            if (tid < 256) {
                int lr = tid >> 5, lc = (tid & 31) * 4;
                cp_async16(ring + st * (8 * WLDW) + lr * WLDW + lc,
                           Bg + (size_t)(kt * 8 + lr) * ldB + lc);
            }
        }
        cp_commit();
    };

    issue(0, 0);
    for (int kt = 0; kt < NKT; kt++) {
        cp_wait<0>();
        __syncthreads();               // stage (kt+1)&1 free for refill
        if (kt + 1 < NKT) issue(kt + 1, (kt + 1) & 1);

        const float* W = ring + (kt & 1) * (8 * WLDW);
        int kc = kt * 8 + quad;
        unsigned bf[NI][2];
        #pragma unroll
        for (int ni = 0; ni < NI; ni++) {
            int n = warp * NSL + ni * 8 + grp;
            bf[ni][0] = __float_as_uint(W[quad * WLDW + n]);
            bf[ni][1] = __float_as_uint(W[(quad + 4) * WLDW + n]);
        }
        #pragma unroll
        for (int mi = 0; mi < 2; mi++) {
            int m = mi * 16 + grp;
            unsigned a0 = __float_as_uint(Asm[m * ALDW + kc]);
            unsigned a1 = __float_as_uint(Asm[(m + 8) * ALDW + kc]);
            unsigned a2 = __float_as_uint(Asm[m * ALDW + kc + 4]);
            unsigned a3 = __float_as_uint(Asm[(m + 8) * ALDW + kc + 4]);
            #pragma unroll
            for (int ni = 0; ni < NI; ni++) {
                asm volatile(
                    "mma.sync.aligned.m16n8k8.row.col.f32.tf32.tf32.f32 "
                    "{%0,%1,%2,%3}, {%4,%5,%6,%7}, {%8,%9}, {%0,%1,%2,%3};"
                    : "+f"(c[mi][ni][0]), "+f"(c[mi][ni][1]),
                      "+f"(c[mi][ni][2]), "+f"(c[mi][ni][3])
                    : "r"(a0), "r"(a1), "r"(a2), "r"(a3),
                      "r"(bf[ni][0]), "r"(bf[ni][1]));
            }
        }
    }

    __syncthreads();   // guard: allows C to alias A (in-place Q)
    #pragma unroll
    for (int mi = 0; mi < 2; mi++) {
        #pragma unroll
        for (int ni = 0; ni < NI; ni++) {
            int colb = warp * NSL + ni * 8 + quad * 2;
            float v0 = c[mi][ni][0] + bias[colb];
            float v1 = c[mi][ni][1] + bias[colb + 1];
            float v2 = c[mi][ni][2] + bias[colb];
            float v3 = c[mi][ni][3] + bias[colb + 1];
            int r0 = mi * 16 + grp;
            int r1 = r0 + 8;
            if (EPI == 3) {
                __nv_bfloat16* cb = (__nv_bfloat16*)Cs;
                if (r0 < 27)
                    *(__nv_bfloat162*)(cb + r0 * KLDE + colb) =
                        __floats2bfloat162_rn(v0, v1);
                if (r1 < 27)
                    *(__nv_bfloat162*)(cb + r1 * KLDE + colb) =
                        __floats2bfloat162_rn(v2, v3);
            } else {
                const float is2 = 0.70710678118654752f;
                if (r0 < 27) {
                    int i0 = r0 * CLDW + colb;
                    if (EPI == 0)      { Cs[i0] = v0; Cs[i0 + 1] = v1; }
                    else if (EPI == 1) { Cs[i0] += v0; Cs[i0 + 1] += v1; }
                    else {
                        Cs[i0]     = 0.5f * v0 * (1.0f + erff(v0 * is2));
                        Cs[i0 + 1] = 0.5f * v1 * (1.0f + erff(v1 * is2));
                    }
                }
                if (r1 < 27) {
                    int i1 = r1 * CLDW + colb;
                    if (EPI == 0)      { Cs[i1] = v2; Cs[i1 + 1] = v3; }
                    else if (EPI == 1) { Cs[i1] += v2; Cs[i1 + 1] += v3; }
                    else {
                        Cs[i1]     = 0.5f * v2 * (1.0f + erff(v2 * is2));
                        Cs[i1 + 1] = 0.5f * v3 * (1.0f + erff(v3 * is2));
                    }
                }
            }
        }
    }
    __syncthreads();
}

// ---------------- CTA layernorm: 32 rows, 16 warps (2 rows each) --------------
__device__ __forceinline__ void cta_ln(const float* __restrict__ x,
                                       const float* __restrict__ g,
                                       const float* __restrict__ bta,
                                       float* __restrict__ y) {
    int tid = threadIdx.x, warp = tid >> 5, lane = tid & 31;
    #pragma unroll
    for (int it = 0; it < 2; it++) {
        int r = warp + it * 16;
        const float* xr = x + r * TLDW + lane * 8;
        float4 v0 = *(const float4*)&xr[0];
        float4 v1 = *(const float4*)&xr[4];
        float s  = v0.x + v0.y + v0.z + v0.w + v1.x + v1.y + v1.z + v1.w;
        float ss = v0.x*v0.x + v0.y*v0.y + v0.z*v0.z + v0.w*v0.w
                 + v1.x*v1.x + v1.y*v1.y + v1.z*v1.z + v1.w*v1.w;
        #pragma unroll
        for (int off = 16; off > 0; off >>= 1) {
            s  += __shfl_xor_sync(0xffffffffu, s,  off);
            ss += __shfl_xor_sync(0xffffffffu, ss, off);
        }
        float mu  = s * (1.0f / DMODEL);
        float var = ss * (1.0f / DMODEL) - mu * mu;
        float rs  = rsqrtf(var + 1e-5f);
        float* yr = y + r * TLDW;
        #pragma unroll
        for (int j = 0; j < 8; j++) {
            int cc = lane * 8 + j;
            float xv = (j < 4) ? ((const float*)&v0)[j] : ((const float*)&v1)[j - 4];
            yr[cc] = (xv - mu) * rs * g[cc] + bta[cc];
        }
    }
}

// ---------------- attention: warps 0..7 = heads, lane = query -----------------
// Two passes over head-dim in both phases to stay under the 64-reg cap.
__device__ __noinline__ void cta_attn(float* __restrict__ x,
                                      const __nv_bfloat16* __restrict__ kb,
                                      const __nv_bfloat16* __restrict__ vb,
                                      const unsigned char* __restrict__ msk,
                                      const unsigned char* __restrict__ nbrt) {
    int tid  = threadIdx.x;
    int warp = tid >> 5;
    int r    = tid & 31;
    if (warp >= 8 || r >= NV) return;
    int h = warp;
    const float scale = 0.17677669529663687f;

    const unsigned char* mr = msk  + r * 28;
    const unsigned char* nr = nbrt + r * 28;

    float s[NV];
    #pragma unroll
    for (int l = 0; l < NV; l++) s[l] = 0.0f;

    // score accumulation, head-dim halves of 16
    #pragma unroll
    for (int half = 0; half < 2; half++) {
        float4 q4[4];
        #pragma unroll
        for (int i = 0; i < 4; i++)
            q4[i] = *(const float4*)&x[r * TLDW + h * 32 + half * 16 + i * 4];
        #pragma unroll
        for (int l = 0; l < NV; l++) {
            if (mr[l]) {
                const __nv_bfloat162* kr = (const __nv_bfloat162*)
                    (kb + nr[l] * KLDE + h * 32 + half * 16);
                float acc = 0.0f;
                #pragma unroll
                for (int i = 0; i < 4; i++) {
                    float2 a = __bfloat1622float2(kr[2 * i]);
                    float2 b = __bfloat1622float2(kr[2 * i + 1]);
                    const float* q = (const float*)&q4[i];
                    acc += q[0] * a.x + q[1] * a.y + q[2] * b.x + q[3] * b.y;
                }
                s[l] += acc;
            }
        }
    }
    // masked softmax
    float mx = -1e30f;
    #pragma unroll
    for (int l = 0; l < NV; l++)
        if (mr[l]) { s[l] *= scale; mx = fmaxf(mx, s[l]); }
    float sum = 0.0f;
    #pragma unroll
    for (int l = 0; l < NV; l++) {
        float w = mr[l] ? expf(s[l] - mx) : 0.0f;
        s[l] = w;
        sum += w;
    }
    float inv = (sum > 0.0f) ? (1.0f / sum) : 0.0f;

    // output, head-dim halves of 16 (in place over own q slice)
    #pragma unroll
    for (int half = 0; half < 2; half++) {
        float o[16];
        #pragma unroll
        for (int i = 0; i < 16; i++) o[i] = 0.0f;
        #pragma unroll
        for (int l = 0; l < NV; l++) {
            if (s[l] > 0.0f) {
                const __nv_bfloat162* vr = (const __nv_bfloat162*)
                    (vb + nr[l] * KLDE + h * 32 + half * 16);
                float w = s[l];
                #pragma unroll
                for (int i = 0; i < 8; i++) {
                    float2 vv = __bfloat1622float2(vr[i]);
                    o[2 * i]     += w * vv.x;
                    o[2 * i + 1] += w * vv.y;
                }
            }
        }
        #pragma unroll
        for (int i = 0; i < 16; i++)
            x[r * TLDW + h * 32 + half * 16 + i] = o[i] * inv;
    }
}

// ---------------- megakernel: one CTA per patch, 2 CTAs per SM ----------------
__global__ void __launch_bounds__(THREADS, 2)
mega_kernel(const float* __restrict__ patch, const void* __restrict__ km_raw,
            const float* __restrict__ w_in, const float* __restrict__ b_in,
            const float* __restrict__ pos,
            const float* __restrict__ ln1_g, const float* __restrict__ ln1_b,
            const float* __restrict__ ln2_g, const float* __restrict__ ln2_b,
            const float* __restrict__ Wq, const float* __restrict__ bq,
            const float* __restrict__ Wk, const float* __restrict__ bk,
            const float* __restrict__ Wv, const float* __restrict__ bv,
            const float* __restrict__ Wo, const float* __restrict__ bo,
            const float* __restrict__ W1, const float* __restrict__ b1,
            const float* __restrict__ W2, const float* __restrict__ b2,
            const float* __restrict__ w_out, const float* __restrict__ b_out,
            float* __restrict__ out) {
    extern __shared__ char sm[];
    float* t    = (float*)(sm + B_T);
    float* x    = (float*)(sm + B_X);
    __nv_bfloat16* kb = (__nv_bfloat16*)(sm + B_KV);
    __nv_bfloat16* vb = (__nv_bfloat16*)(sm + B_V);
    float* hbuf = (float*)(sm + B_KV);      // overlays k/v during FFN
    float* ring = (float*)(sm + B_RING);
    unsigned char* msk  = (unsigned char*)(sm + B_MSK);
    unsigned char* nbrt = (unsigned char*)(sm + B_NBR);

    int b   = blockIdx.x;
    int tid = threadIdx.x;

    // ---- embed (rows 27..31 zero) ----
    for (int idx = tid; idx < 32 * DMODEL; idx += THREADS) {
        int row = idx >> 8, cc = idx & 255;
        t[row * TLDW + cc] = (row < NV)
            ? patch[b * NV + row] * w_in[cc] + b_in[cc] + pos[row * DMODEL + cc]
            : 0.0f;
    }

    // ---- neighbor table + mask ----
    int mode = g_mode;
    for (int idx = tid; idx < NV * NV; idx += THREADS) {
        int r = idx / NV, l = idx % NV;
        int zc = r / 9, yc = (r / 3) % 3, xc = r % 3;
        int z = zc + l / 9 - 1, y = yc + (l / 3) % 3 - 1, xx = xc + l % 3 - 1;
        bool in = ((unsigned)z < 3u) && ((unsigned)y < 3u) && ((unsigned)xx < 3u);
        int j = in ? (z * 9 + y * 3 + xx) : 0;
        bool kv = false;
        if (in) {
            int gi = b * NV + j;
            if (mode == 0)      kv = ((const unsigned char*)km_raw)[gi] != 0;
            else if (mode == 1) kv = ((const int*)km_raw)[gi] != 0;
            else                kv = ((const float*)km_raw)[gi] != 0.0f;
        }
        msk[r * 28 + l]  = kv ? 1 : 0;
        nbrt[r * 28 + l] = (unsigned char)j;
    }
    __syncthreads();

    for (int l = 0; l < NLAYERS; l++) {
        const float* wq = Wq + (size_t)l * DMODEL * DMODEL;
        const float* wk = Wk + (size_t)l * DMODEL * DMODEL;
        const float* wv = Wv + (size_t)l * DMODEL * DMODEL;
        const float* wo = Wo + (size_t)l * DMODEL * DMODEL;
        const float* w1 = W1 + (size_t)l * DMODEL * FFDIM;
        const float* w2 = W2 + (size_t)l * FFDIM * DMODEL;

        // LN1(t) -> x ; Q = x@Wq in place ; K/V from t -> bf16
        cta_ln(t, ln1_g + l * DMODEL, ln1_b + l * DMODEL, x);
        __syncthreads();
        cta_gemm<0, 32, 256, TLDW, TLDW>(x, wq, DMODEL, bq + l * DMODEL, x, ring);
        cta_gemm<3, 32, 256, TLDW, 0>(t, wk, DMODEL, bk + l * DMODEL,
                                      (float*)kb, ring);
        cta_gemm<3, 32, 256, TLDW, 0>(t, wv, DMODEL, bv + l * DMODEL,
                                      (float*)vb, ring);

        cta_attn(x, kb, vb, msk, nbrt);
        __syncthreads();

        // t += x @ Wo + bo
        cta_gemm<1, 32, 256, TLDW, TLDW>(x, wo, DMODEL, bo + l * DMODEL, t, ring);

        // FFN in 8 chunks of 128
        cta_ln(t, ln2_g + l * DMODEL, ln2_b + l * DMODEL, x);
        __syncthreads();
        for (int cch = 0; cch < 8; cch++) {
            cta_gemm<2, 32, 128, TLDW, HLDW>(x, w1 + cch * 128, FFDIM,
                                             b1 + l * FFDIM + cch * 128,
                                             hbuf, ring);
            cta_gemm<1, 16, 256, HLDW, TLDW>(hbuf,
                                             w2 + (size_t)(cch * 128) * DMODEL,
                                             DMODEL,
                                             (cch == 0) ? (b2 + l * DMODEL)
                                                        : g_zero,
                                             t, ring);
        }
    }

    // ---- readout: out[b] = t[13] . w_out + b_out ----
    {
        float v = (tid < DMODEL) ? t[13 * TLDW + tid] * w_out[tid] : 0.0f;
        #pragma unroll
        for (int off = 16; off > 0; off >>= 1)
            v += __shfl_xor_sync(0xffffffffu, v, off);
        if ((tid & 31) == 0 && tid < DMODEL) ring[tid >> 5] = v;
        __syncthreads();
        if (tid == 0) {
            float s = 0.0f;
            #pragma unroll
            for (int w = 0; w < 8; w++) s += ring[w];
            out[b] = s + b_out[0];
        }
    }
}

// ---------------- driver -----------------------------------------------------
extern "C" void kernel_launch(void* const* d_in, const int* in_sizes, int n_in,
                              void* d_out, int out_size) {
    const float* patch   = (const float*)d_in[0];
    const void*  km      = d_in[1];
    const float* w_in    = (const float*)d_in[2];
    const float* b_in    = (const float*)d_in[3];
    const float* pos     = (const float*)d_in[4];
    const float* ln1_g   = (const float*)d_in[5];
    const float* ln1_b   = (const float*)d_in[6];
    const float* ln2_g   = (const float*)d_in[7];
    const float* ln2_b   = (const float*)d_in[8];
    const float* Wq      = (const float*)d_in[9];
    const float* bq      = (const float*)d_in[10];
    const float* Wk      = (const float*)d_in[11];
    const float* bk      = (const float*)d_in[12];
    const float* Wv      = (const float*)d_in[13];
    const float* bv      = (const float*)d_in[14];
    const float* Wo      = (const float*)d_in[15];
    const float* bo      = (const float*)d_in[16];
    const float* W1      = (const float*)d_in[17];
    const float* b1      = (const float*)d_in[18];
    const float* W2      = (const float*)d_in[19];
    const float* b2      = (const float*)d_in[20];
    const float* w_out   = (const float*)d_in[21];
    const float* b_out   = (const float*)d_in[22];
    float* out = (float*)d_out;

    static int configured = 0;
    if (!configured) {
        cudaFuncSetAttribute(mega_kernel,
                             cudaFuncAttributeMaxDynamicSharedMemorySize,
                             SMEM_BYTES);
        configured = 1;
    }

    detect_kernel<<<1, 256>>>((const unsigned char*)km);
    mega_kernel<<<BATCH, THREADS, SMEM_BYTES>>>(
        patch, km, w_in, b_in, pos,
        ln1_g, ln1_b, ln2_g, ln2_b,
        Wq, bq, Wk, bk, Wv, bv, Wo, bo,
        W1, b1, W2, b2, w_out, b_out, out);
}